// round 13
// baseline (speedup 1.0000x reference)
#include <cuda_runtime.h>
#include <cuda_bf16.h>
#include <cuda_fp16.h>
#include <math.h>

// Fixed problem shape
#define BB   4
#define NN   32768
#define KK   16
#define CIN  32
#define HH   32
#define COUT 32
#define PP   3

#define GTOT (BB * NN)          // 131072 nodes
#define ETOT (BB * NN * KK)     // 2097152 edges
#define MELEMS (GTOT * HH)      // 4194304 elements

// Scratch (__device__ globals; no allocation allowed)
__device__ __half  g_mh[MELEMS];    // m[node,h] fp16 (8 MB)
__device__ __half  g_acch[MELEMS];  // segment-sum accumulator fp16 (8 MB)
__device__ float4  g_grid4[GTOT];   // packed grid coords

// Packed weights (pack_kernel fills g_pack; one D2D memcpy -> c_pack)
struct Pack {
    float2 w1t[CIN * (HH / 2)];    // [c][hp] = {W1[2hp,c], W1[2hp+1,c]}
    float2 w2t[HH * (COUT / 2)];   // [h][op] = {W2[2op,h], W2[2op+1,h]}
    float  b1[HH];
    float  sc[HH];                 // sqrt((bw/pi)^3)
    float  nb[HH];                 // -bw * log2(e)
    float  b2[COUT];
};
__device__  Pack g_pack;
__constant__ Pack c_pack;

// ---- f32x2 helpers ----
__device__ __forceinline__ unsigned long long pk2(float lo, float hi) {
    unsigned long long r;
    asm("mov.b64 %0, {%1,%2};" : "=l"(r) : "f"(lo), "f"(hi));
    return r;
}
__device__ __forceinline__ float2 upk2(unsigned long long v) {
    float2 r;
    asm("mov.b64 {%0,%1}, %2;" : "=f"(r.x), "=f"(r.y) : "l"(v));
    return r;
}
__device__ __forceinline__ void ffma2(unsigned long long& acc,
                                      unsigned long long a,
                                      unsigned long long b) {
    asm("fma.rn.f32x2 %0, %1, %2, %0;" : "+l"(acc) : "l"(a), "l"(b));
}

// ---------------------------------------------------------------------------
// Prep: pack W1/W2 pairs + fold bw transforms. One block.
// ---------------------------------------------------------------------------
__global__ void pack_kernel(const float* __restrict__ W1,
                            const float* __restrict__ b1,
                            const float* __restrict__ W2,
                            const float* __restrict__ b2,
                            const float* __restrict__ bw) {
    int t = threadIdx.x;
    for (int i = t; i < CIN * (HH / 2); i += blockDim.x) {
        int c  = i / (HH / 2);
        int hp = i % (HH / 2);
        g_pack.w1t[i] = make_float2(W1[(2 * hp) * CIN + c],
                                    W1[(2 * hp + 1) * CIN + c]);
    }
    for (int i = t; i < HH * (COUT / 2); i += blockDim.x) {
        int h  = i / (COUT / 2);
        int op = i % (COUT / 2);
        g_pack.w2t[i] = make_float2(W2[(2 * op) * HH + h],
                                    W2[(2 * op + 1) * HH + h]);
    }
    if (t < HH) {
        g_pack.b1[t] = b1[t];
        float w = bw[t];
        float r = w * 0.3183098861837907f;          // bw/pi
        g_pack.sc[t] = sqrtf(r * r * r);
        g_pack.nb[t] = -w * 1.4426950408889634f;    // -bw*log2e
        g_pack.b2[t] = b2[t];
    }
}

// ---------------------------------------------------------------------------
// gemm1 fused (1 node/thread, f32x2, weights in SHARED — broadcast LDS.128
// instead of LDC floor-8):
//   m_h[g,h] = half((W1x+b1)*gw*sc[h]) ; acch[g,:]=0 ; grid4 pack.
// ---------------------------------------------------------------------------
__global__ void gemm1_kernel(const float* __restrict__ x,
                             const float* __restrict__ gw,
                             const float* __restrict__ grid) {
    __shared__ __align__(16) float2 sW1[CIN * (HH / 2)];   // 4 KB
    int t = threadIdx.x;
    sW1[t]       = c_pack.w1t[t];
    sW1[t + 256] = c_pack.w1t[t + 256];
    __syncthreads();

    int g = blockIdx.x * blockDim.x + t;             // node id
    int b = g >> 15;                                 // NN = 2^15
    int n = g & (NN - 1);
    const float* xb = x + (size_t)b * CIN * NN + n;

    const ulonglong2* w1v = reinterpret_cast<const ulonglong2*>(sW1);

    unsigned long long acc2[HH / 2];
#pragma unroll
    for (int hp = 0; hp < HH / 2; hp++) acc2[hp] = 0ull;

#pragma unroll
    for (int c = 0; c < CIN; c++) {
        float xv = xb[(size_t)c * NN];               // coalesced
        unsigned long long xx = pk2(xv, xv);
#pragma unroll
        for (int q = 0; q < 8; q++) {                // 8 x LDS.128 broadcast
            ulonglong2 wv = w1v[c * 8 + q];
            ffma2(acc2[2 * q],     wv.x, xx);
            ffma2(acc2[2 * q + 1], wv.y, xx);
        }
    }

    float w = gw[g];
    uint4 ov[4];                                     // 32 halves = 64 B
    unsigned int* oh = reinterpret_cast<unsigned int*>(ov);
#pragma unroll
    for (int hp = 0; hp < HH / 2; hp++) {
        float2 a = upk2(acc2[hp]);
        float m0 = (a.x + c_pack.b1[2 * hp])     * w * c_pack.sc[2 * hp];
        float m1 = (a.y + c_pack.b1[2 * hp + 1]) * w * c_pack.sc[2 * hp + 1];
        __half2 h2 = __floats2half2_rn(m0, m1);
        oh[hp] = *reinterpret_cast<unsigned int*>(&h2);
    }
    uint4* mo = reinterpret_cast<uint4*>(g_mh + (size_t)g * HH);
#pragma unroll
    for (int q = 0; q < 4; q++) mo[q] = ov[q];

    // zero fp16 accumulator row (64 B)
    uint4* ao = reinterpret_cast<uint4*>(g_acch + (size_t)g * HH);
#pragma unroll
    for (int q = 0; q < 4; q++) ao[q] = make_uint4(0, 0, 0, 0);

    const float* gp = grid + (size_t)g * PP;
    g_grid4[g] = make_float4(gp[0], gp[1], gp[2], 0.f);
}

// ---------------------------------------------------------------------------
// Edge kernel — unchanged (at LTS-sector floor). Warp owns 32 edges;
// phase 2 retires 8 edges/iter via red.global.add.noftz.v4.f16x2.
// ---------------------------------------------------------------------------
__global__ void edge_kernel(const int* __restrict__ es,
                            const int* __restrict__ ed) {
    __shared__ float4 stage[8][32];                  // 8 warps/block
    int tid  = blockIdx.x * blockDim.x + threadIdx.x;
    int lane = threadIdx.x & 31;
    int w    = threadIdx.x >> 5;

    // ---- phase 1: lane = edge ----
    int e   = tid;
    int b   = e >> 19;                               // NN*KK = 2^19
    int off = b << 15;                               // b * NN
    int s   = __ldg(es + e) + off;
    int d   = __ldg(ed + e) + off;

    float4 gs = g_grid4[s];
    float4 gd = g_grid4[d];
    float dx = gs.x - gd.x;
    float dy = gs.y - gd.y;
    float dz = gs.z - gd.z;
    float d2 = dx * dx + dy * dy + dz * dz;

    stage[w][lane] = make_float4(__int_as_float(s * HH),
                                 __int_as_float(d * HH), d2, 0.f);
    __syncwarp();

    // ---- phase 2: grp = edge of oct, c0 = first of 8 channels ----
    int grp = lane >> 2;                             // 0..7
    int c0  = (lane & 3) * 8;                        // 0,8,16,24

    float nb[8];
#pragma unroll
    for (int j = 0; j < 8; j++) nb[j] = c_pack.nb[c0 + j];

#pragma unroll
    for (int i = 0; i < 32; i += 8) {
        float4 p  = stage[w][i + grp];               // 8-way LDS.128 broadcast
        int   si  = __float_as_int(p.x);
        int   di  = __float_as_int(p.y);
        float d2i = p.z;

        uint4 mraw = *reinterpret_cast<const uint4*>(g_mh + si + c0);
        const __half2* mh2 = reinterpret_cast<const __half2*>(&mraw);

        unsigned int vpk[4];
#pragma unroll
        for (int j = 0; j < 4; j++) {
            float2 mf = __half22float2(mh2[j]);
            float e0, e1;
            asm("ex2.approx.f32 %0, %1;" : "=f"(e0) : "f"(nb[2 * j] * d2i));
            asm("ex2.approx.f32 %0, %1;" : "=f"(e1) : "f"(nb[2 * j + 1] * d2i));
            __half2 h2 = __floats2half2_rn(mf.x * e0, mf.y * e1);
            vpk[j] = *reinterpret_cast<unsigned int*>(&h2);
        }

        asm volatile("red.global.add.noftz.v4.f16x2 [%0], {%1, %2, %3, %4};"
                     :: "l"(g_acch + di + c0),
                        "r"(vpk[0]), "r"(vpk[1]), "r"(vpk[2]), "r"(vpk[3])
                     : "memory");
    }
}

// ---------------------------------------------------------------------------
// gemm2: TWO adjacent nodes per thread, weights in SHARED (broadcast LDS.128).
// Each LDS.128 fetches two weight-pairs feeding four FFMA2s.
// ---------------------------------------------------------------------------
__global__ void gemm2_kernel(float* __restrict__ out) {
    __shared__ __align__(16) float2 sW2[HH * (COUT / 2)];  // 4 KB
    int tt = threadIdx.x;                            // 128 threads/block
#pragma unroll
    for (int i = 0; i < 4; i++) sW2[tt + 128 * i] = c_pack.w2t[tt + 128 * i];
    __syncthreads();

    int t  = blockIdx.x * blockDim.x + tt;           // pair id [0, GTOT/2)
    int g0 = 2 * t;                                  // nodes g0, g0+1 (same batch)
    int b  = g0 >> 15;
    int n  = g0 & (NN - 1);

    // load both fp16 acc rows (128 B contiguous)
    const uint4* av = reinterpret_cast<const uint4*>(g_acch + (size_t)g0 * HH);
    uint4 ra[8];
#pragma unroll
    for (int q = 0; q < 8; q++) ra[q] = av[q];
    const __half2* h0 = reinterpret_cast<const __half2*>(&ra[0]);  // node0
    const __half2* h1 = reinterpret_cast<const __half2*>(&ra[4]);  // node1

    const ulonglong2* w2v = reinterpret_cast<const ulonglong2*>(sW2);

    unsigned long long sA[COUT / 2], sB[COUT / 2];   // per-node output pairs
#pragma unroll
    for (int op = 0; op < COUT / 2; op++) {
        unsigned long long binit = pk2(c_pack.b2[2 * op], c_pack.b2[2 * op + 1]);
        sA[op] = binit;
        sB[op] = binit;
    }

#pragma unroll
    for (int hp = 0; hp < HH / 2; hp++) {
        float2 f0 = __half22float2(h0[hp]);          // a0[2hp], a0[2hp+1]
        float2 f1 = __half22float2(h1[hp]);
        unsigned long long a0e = pk2(f0.x, f0.x);
        unsigned long long a0o = pk2(f0.y, f0.y);
        unsigned long long a1e = pk2(f1.x, f1.x);
        unsigned long long a1o = pk2(f1.y, f1.y);
        int he = 2 * hp, ho = 2 * hp + 1;
#pragma unroll
        for (int q = 0; q < 8; q++) {                // broadcast LDS.128
            ulonglong2 wv = w2v[he * 8 + q];
            ffma2(sA[2 * q],     wv.x, a0e);
            ffma2(sB[2 * q],     wv.x, a1e);
            ffma2(sA[2 * q + 1], wv.y, a0e);
            ffma2(sB[2 * q + 1], wv.y, a1e);
        }
#pragma unroll
        for (int q = 0; q < 8; q++) {
            ulonglong2 wv = w2v[ho * 8 + q];
            ffma2(sA[2 * q],     wv.x, a0o);
            ffma2(sB[2 * q],     wv.x, a1o);
            ffma2(sA[2 * q + 1], wv.y, a0o);
            ffma2(sB[2 * q + 1], wv.y, a1o);
        }
    }

    float* ob = out + (size_t)b * COUT * NN + n;
#pragma unroll
    for (int op = 0; op < COUT / 2; op++) {
        float2 vA = upk2(sA[op]);                    // node0: out[2op], out[2op+1]
        float2 vB = upk2(sB[op]);                    // node1
        *reinterpret_cast<float2*>(ob + (size_t)(2 * op) * NN) =
            make_float2(vA.x, vB.x);
        *reinterpret_cast<float2*>(ob + (size_t)(2 * op + 1) * NN) =
            make_float2(vA.y, vB.y);
    }
}

// ---------------------------------------------------------------------------
// Launcher
// inputs: 0:x 1:grid 2:grid_weight 3:edge_src 4:edge_dst 5:W1 6:b1 7:W2 8:b2 9:baseweight
// ---------------------------------------------------------------------------
extern "C" void kernel_launch(void* const* d_in, const int* in_sizes, int n_in,
                              void* d_out, int out_size) {
    const float* x    = (const float*)d_in[0];
    const float* grid = (const float*)d_in[1];
    const float* gw   = (const float*)d_in[2];
    const int*   es   = (const int*)d_in[3];
    const int*   ed   = (const int*)d_in[4];
    const float* W1   = (const float*)d_in[5];
    const float* b1   = (const float*)d_in[6];
    const float* W2   = (const float*)d_in[7];
    const float* b2   = (const float*)d_in[8];
    const float* bw   = (const float*)d_in[9];
    float* out = (float*)d_out;

    // 0) pack weights on device, stage into constant bank (single D2D copy)
    pack_kernel<<<1, 256>>>(W1, b1, W2, b2, bw);
    void* packAddr = nullptr;
    cudaGetSymbolAddress(&packAddr, g_pack);
    cudaMemcpyToSymbolAsync(c_pack, packAddr, sizeof(Pack), 0,
                            cudaMemcpyDeviceToDevice, 0);

    // 1) fused fc1 (f32x2, shared weights) ; zero acc ; pack grid
    gemm1_kernel<<<GTOT / 256, 256>>>(x, gw, grid);

    // 2) edge scatter: 32 edges per warp, two-phase, RED.v4.f16x2
    edge_kernel<<<ETOT / 256, 256>>>(es, ed);

    // 3) fc2 (f32x2, 2 nodes/thread, shared weights) + transpose
    gemm2_kernel<<<(GTOT / 2) / 128, 128>>>(out);
}

// round 14
// speedup vs baseline: 1.0791x; 1.0791x over previous
#include <cuda_runtime.h>
#include <cuda_bf16.h>
#include <cuda_fp16.h>
#include <math.h>

// Fixed problem shape
#define BB   4
#define NN   32768
#define KK   16
#define CIN  32
#define HH   32
#define COUT 32
#define PP   3

#define GTOT (BB * NN)          // 131072 nodes
#define ETOT (BB * NN * KK)     // 2097152 edges
#define MELEMS (GTOT * HH)      // 4194304 elements

// Scratch (__device__ globals; no allocation allowed)
__device__ __half  g_mh[MELEMS];    // m[node,h] fp16 (8 MB)
__device__ __half  g_acch[MELEMS];  // segment-sum accumulator fp16 (8 MB)
__device__ float4  g_grid4[GTOT];   // packed grid coords

// Packed weights (pack_kernel fills g_pack; one D2D memcpy -> c_pack)
struct Pack {
    float2 w1t[CIN * (HH / 2)];    // [c][hp] = {W1[2hp,c], W1[2hp+1,c]}
    float2 w2t[HH * (COUT / 2)];   // [h][op] = {W2[2op,h], W2[2op+1,h]}
    float  b1[HH];
    float  sc[HH];                 // sqrt((bw/pi)^3)
    float  nb[HH];                 // -bw * log2(e)
    float  b2[COUT];
};
__device__  Pack g_pack;
__constant__ Pack c_pack;

// ---- f32x2 helpers ----
__device__ __forceinline__ unsigned long long pk2(float lo, float hi) {
    unsigned long long r;
    asm("mov.b64 %0, {%1,%2};" : "=l"(r) : "f"(lo), "f"(hi));
    return r;
}
__device__ __forceinline__ float2 upk2(unsigned long long v) {
    float2 r;
    asm("mov.b64 {%0,%1}, %2;" : "=f"(r.x), "=f"(r.y) : "l"(v));
    return r;
}
__device__ __forceinline__ void ffma2(unsigned long long& acc,
                                      unsigned long long a,
                                      unsigned long long b) {
    asm("fma.rn.f32x2 %0, %1, %2, %0;" : "+l"(acc) : "l"(a), "l"(b));
}

// ---------------------------------------------------------------------------
// Prep: pack W1/W2 pairs + fold bw transforms. One block.
// ---------------------------------------------------------------------------
__global__ void pack_kernel(const float* __restrict__ W1,
                            const float* __restrict__ b1,
                            const float* __restrict__ W2,
                            const float* __restrict__ b2,
                            const float* __restrict__ bw) {
    int t = threadIdx.x;
    for (int i = t; i < CIN * (HH / 2); i += blockDim.x) {
        int c  = i / (HH / 2);
        int hp = i % (HH / 2);
        g_pack.w1t[i] = make_float2(W1[(2 * hp) * CIN + c],
                                    W1[(2 * hp + 1) * CIN + c]);
    }
    for (int i = t; i < HH * (COUT / 2); i += blockDim.x) {
        int h  = i / (COUT / 2);
        int op = i % (COUT / 2);
        g_pack.w2t[i] = make_float2(W2[(2 * op) * HH + h],
                                    W2[(2 * op + 1) * HH + h]);
    }
    if (t < HH) {
        g_pack.b1[t] = b1[t];
        float w = bw[t];
        float r = w * 0.3183098861837907f;          // bw/pi
        g_pack.sc[t] = sqrtf(r * r * r);
        g_pack.nb[t] = -w * 1.4426950408889634f;    // -bw*log2e
        g_pack.b2[t] = b2[t];
    }
}

// ---------------------------------------------------------------------------
// gemm1 fused: TWO nodes per thread (g and g+GTOT/2), f32x2, constant weights.
// Each weight LDCU feeds four FFMA2s (2 nodes x f32x2 pair).
//   m_h[g,h] = half((W1x+b1)*gw*sc[h]) ; acch[g,:]=0 ; grid4 pack.
// ---------------------------------------------------------------------------
__global__ void gemm1_kernel(const float* __restrict__ x,
                             const float* __restrict__ gw,
                             const float* __restrict__ grid) {
    int i  = blockIdx.x * blockDim.x + threadIdx.x;  // [0, GTOT/2)
    int g0 = i;
    int g1 = i + GTOT / 2;

    const float* xb0 = x + (size_t)(g0 >> 15) * CIN * NN + (g0 & (NN - 1));
    const float* xb1 = x + (size_t)(g1 >> 15) * CIN * NN + (g1 & (NN - 1));

    const unsigned long long* w1u =
        reinterpret_cast<const unsigned long long*>(c_pack.w1t);

    unsigned long long accA[HH / 2], accB[HH / 2];
#pragma unroll
    for (int hp = 0; hp < HH / 2; hp++) { accA[hp] = 0ull; accB[hp] = 0ull; }

#pragma unroll
    for (int c = 0; c < CIN; c++) {
        float xv0 = xb0[(size_t)c * NN];             // coalesced
        float xv1 = xb1[(size_t)c * NN];             // coalesced
        unsigned long long xx0 = pk2(xv0, xv0);
        unsigned long long xx1 = pk2(xv1, xv1);
#pragma unroll
        for (int hp = 0; hp < HH / 2; hp++) {
            unsigned long long wv = w1u[c * (HH / 2) + hp];  // one LDCU
            ffma2(accA[hp], wv, xx0);                        // four uses
            ffma2(accB[hp], wv, xx1);
        }
    }

    float w0 = gw[g0];
    float w1 = gw[g1];

#pragma unroll
    for (int node = 0; node < 2; node++) {
        int g = node ? g1 : g0;
        float wgt = node ? w1 : w0;
        const unsigned long long* acc2 = node ? accB : accA;

        uint4 ov[4];                                 // 32 halves = 64 B
        unsigned int* oh = reinterpret_cast<unsigned int*>(ov);
#pragma unroll
        for (int hp = 0; hp < HH / 2; hp++) {
            float2 a = upk2(acc2[hp]);
            float m0 = (a.x + c_pack.b1[2 * hp])     * wgt * c_pack.sc[2 * hp];
            float m1 = (a.y + c_pack.b1[2 * hp + 1]) * wgt * c_pack.sc[2 * hp + 1];
            __half2 h2 = __floats2half2_rn(m0, m1);
            oh[hp] = *reinterpret_cast<unsigned int*>(&h2);
        }
        uint4* mo = reinterpret_cast<uint4*>(g_mh + (size_t)g * HH);
#pragma unroll
        for (int q = 0; q < 4; q++) mo[q] = ov[q];

        // zero fp16 accumulator row (64 B)
        uint4* ao = reinterpret_cast<uint4*>(g_acch + (size_t)g * HH);
#pragma unroll
        for (int q = 0; q < 4; q++) ao[q] = make_uint4(0, 0, 0, 0);

        const float* gp = grid + (size_t)g * PP;
        g_grid4[g] = make_float4(gp[0], gp[1], gp[2], 0.f);
    }
}

// ---------------------------------------------------------------------------
// Edge kernel — round-12 version (at LTS atomic/sector floor). Warp owns 32
// edges; phase 2 retires 8 edges/iter via red.global.add.noftz.v4.f16x2.
// ---------------------------------------------------------------------------
__global__ void edge_kernel(const int* __restrict__ es,
                            const int* __restrict__ ed) {
    __shared__ float4 stage[8][32];                  // 8 warps/block
    int tid  = blockIdx.x * blockDim.x + threadIdx.x;
    int lane = threadIdx.x & 31;
    int w    = threadIdx.x >> 5;

    // ---- phase 1: lane = edge ----
    int e   = tid;
    int b   = e >> 19;                               // NN*KK = 2^19
    int off = b << 15;                               // b * NN
    int s   = __ldg(es + e) + off;
    int d   = __ldg(ed + e) + off;

    float4 gs = g_grid4[s];
    float4 gd = g_grid4[d];
    float dx = gs.x - gd.x;
    float dy = gs.y - gd.y;
    float dz = gs.z - gd.z;
    float d2 = dx * dx + dy * dy + dz * dz;

    stage[w][lane] = make_float4(__int_as_float(s * HH),
                                 __int_as_float(d * HH), d2, 0.f);
    __syncwarp();

    // ---- phase 2: grp = edge of oct, c0 = first of 8 channels ----
    int grp = lane >> 2;                             // 0..7
    int c0  = (lane & 3) * 8;                        // 0,8,16,24

    float nb[8];
#pragma unroll
    for (int j = 0; j < 8; j++) nb[j] = c_pack.nb[c0 + j];

#pragma unroll
    for (int i = 0; i < 32; i += 8) {
        float4 p  = stage[w][i + grp];               // 8-way LDS.128 broadcast
        int   si  = __float_as_int(p.x);
        int   di  = __float_as_int(p.y);
        float d2i = p.z;

        uint4 mraw = *reinterpret_cast<const uint4*>(g_mh + si + c0);
        const __half2* mh2 = reinterpret_cast<const __half2*>(&mraw);

        unsigned int vpk[4];
#pragma unroll
        for (int j = 0; j < 4; j++) {
            float2 mf = __half22float2(mh2[j]);
            float e0, e1;
            asm("ex2.approx.f32 %0, %1;" : "=f"(e0) : "f"(nb[2 * j] * d2i));
            asm("ex2.approx.f32 %0, %1;" : "=f"(e1) : "f"(nb[2 * j + 1] * d2i));
            __half2 h2 = __floats2half2_rn(mf.x * e0, mf.y * e1);
            vpk[j] = *reinterpret_cast<unsigned int*>(&h2);
        }

        asm volatile("red.global.add.noftz.v4.f16x2 [%0], {%1, %2, %3, %4};"
                     :: "l"(g_acch + di + c0),
                        "r"(vpk[0]), "r"(vpk[1]), "r"(vpk[2]), "r"(vpk[3])
                     : "memory");
    }
}

// ---------------------------------------------------------------------------
// gemm2 — round-12 version (best): TWO adjacent nodes per thread; each weight
// LDCU feeds two FFMA2s. acc rows = 128B contiguous; outputs STG.64.
// ---------------------------------------------------------------------------
__global__ void gemm2_kernel(float* __restrict__ out) {
    int t  = blockIdx.x * blockDim.x + threadIdx.x;  // pair id [0, GTOT/2)
    int g0 = 2 * t;                                  // nodes g0, g0+1 (same batch)
    int b  = g0 >> 15;
    int n  = g0 & (NN - 1);

    // load both fp16 acc rows (128 B contiguous)
    const uint4* av = reinterpret_cast<const uint4*>(g_acch + (size_t)g0 * HH);
    uint4 ra[8];
#pragma unroll
    for (int q = 0; q < 8; q++) ra[q] = av[q];
    const __half2* h0 = reinterpret_cast<const __half2*>(&ra[0]);  // node0
    const __half2* h1 = reinterpret_cast<const __half2*>(&ra[4]);  // node1

    const unsigned long long* w2u =
        reinterpret_cast<const unsigned long long*>(c_pack.w2t);

    unsigned long long sA[COUT / 2], sB[COUT / 2];   // per-node output pairs
#pragma unroll
    for (int op = 0; op < COUT / 2; op++) {
        unsigned long long binit = pk2(c_pack.b2[2 * op], c_pack.b2[2 * op + 1]);
        sA[op] = binit;
        sB[op] = binit;
    }

#pragma unroll
    for (int hp = 0; hp < HH / 2; hp++) {
        float2 f0 = __half22float2(h0[hp]);          // a0[2hp], a0[2hp+1]
        float2 f1 = __half22float2(h1[hp]);
        unsigned long long a0e = pk2(f0.x, f0.x);
        unsigned long long a0o = pk2(f0.y, f0.y);
        unsigned long long a1e = pk2(f1.x, f1.x);
        unsigned long long a1o = pk2(f1.y, f1.y);
        int he = 2 * hp, ho = 2 * hp + 1;
#pragma unroll
        for (int op = 0; op < COUT / 2; op++) {
            unsigned long long wE = w2u[he * (COUT / 2) + op];  // one LDCU
            ffma2(sA[op], wE, a0e);                              // two uses
            ffma2(sB[op], wE, a1e);
        }
#pragma unroll
        for (int op = 0; op < COUT / 2; op++) {
            unsigned long long wO = w2u[ho * (COUT / 2) + op];
            ffma2(sA[op], wO, a0o);
            ffma2(sB[op], wO, a1o);
        }
    }

    float* ob = out + (size_t)b * COUT * NN + n;
#pragma unroll
    for (int op = 0; op < COUT / 2; op++) {
        float2 vA = upk2(sA[op]);                    // node0: out[2op], out[2op+1]
        float2 vB = upk2(sB[op]);                    // node1
        *reinterpret_cast<float2*>(ob + (size_t)(2 * op) * NN) =
            make_float2(vA.x, vB.x);
        *reinterpret_cast<float2*>(ob + (size_t)(2 * op + 1) * NN) =
            make_float2(vA.y, vB.y);
    }
}

// ---------------------------------------------------------------------------
// Launcher
// inputs: 0:x 1:grid 2:grid_weight 3:edge_src 4:edge_dst 5:W1 6:b1 7:W2 8:b2 9:baseweight
// ---------------------------------------------------------------------------
extern "C" void kernel_launch(void* const* d_in, const int* in_sizes, int n_in,
                              void* d_out, int out_size) {
    const float* x    = (const float*)d_in[0];
    const float* grid = (const float*)d_in[1];
    const float* gw   = (const float*)d_in[2];
    const int*   es   = (const int*)d_in[3];
    const int*   ed   = (const int*)d_in[4];
    const float* W1   = (const float*)d_in[5];
    const float* b1   = (const float*)d_in[6];
    const float* W2   = (const float*)d_in[7];
    const float* b2   = (const float*)d_in[8];
    const float* bw   = (const float*)d_in[9];
    float* out = (float*)d_out;

    // 0) pack weights on device, stage into constant bank (single D2D copy)
    pack_kernel<<<1, 256>>>(W1, b1, W2, b2, bw);
    void* packAddr = nullptr;
    cudaGetSymbolAddress(&packAddr, g_pack);
    cudaMemcpyToSymbolAsync(c_pack, packAddr, sizeof(Pack), 0,
                            cudaMemcpyDeviceToDevice, 0);

    // 1) fused fc1 (f32x2, 2 nodes/thread) ; zero acc ; pack grid
    gemm1_kernel<<<(GTOT / 2) / 256, 256>>>(x, gw, grid);

    // 2) edge scatter: 32 edges per warp, two-phase, RED.v4.f16x2
    edge_kernel<<<ETOT / 256, 256>>>(es, ed);

    // 3) fc2 (f32x2, 2 nodes/thread) + transpose to (B, COUT, N)
    gemm2_kernel<<<(GTOT / 2) / 128, 128>>>(out);
}

// round 15
// speedup vs baseline: 1.0889x; 1.0091x over previous
#include <cuda_runtime.h>
#include <cuda_bf16.h>
#include <cuda_fp16.h>
#include <math.h>

// Fixed problem shape
#define BB   4
#define NN   32768
#define KK   16
#define CIN  32
#define HH   32
#define COUT 32
#define PP   3

#define GTOT (BB * NN)          // 131072 nodes
#define ETOT (BB * NN * KK)     // 2097152 edges
#define MELEMS (GTOT * HH)      // 4194304 elements

// Scratch (__device__ globals; no allocation allowed)
__device__ __half  g_mh[MELEMS];    // m[node,h] fp16 (8 MB)
__device__ __half  g_acch[MELEMS];  // segment-sum accumulator fp16 (8 MB)
__device__ float4  g_grid4[GTOT];   // packed grid coords

// Packed weights (pack_kernel fills g_pack; one D2D memcpy -> c_pack)
struct Pack {
    float2 w1t[CIN * (HH / 2)];    // [c][hp] = {W1[2hp,c], W1[2hp+1,c]}
    float2 w2t[HH * (COUT / 2)];   // [h][op] = {W2[2op,h], W2[2op+1,h]}
    float  b1[HH];
    float  sc[HH];                 // sqrt((bw/pi)^3)
    float  nb[HH];                 // -bw * log2(e)
    float  b2[COUT];
};
__device__  Pack g_pack;
__constant__ Pack c_pack;

// ---- f32x2 helpers ----
__device__ __forceinline__ unsigned long long pk2(float lo, float hi) {
    unsigned long long r;
    asm("mov.b64 %0, {%1,%2};" : "=l"(r) : "f"(lo), "f"(hi));
    return r;
}
__device__ __forceinline__ float2 upk2(unsigned long long v) {
    float2 r;
    asm("mov.b64 {%0,%1}, %2;" : "=f"(r.x), "=f"(r.y) : "l"(v));
    return r;
}
__device__ __forceinline__ void ffma2(unsigned long long& acc,
                                      unsigned long long a,
                                      unsigned long long b) {
    asm("fma.rn.f32x2 %0, %1, %2, %0;" : "+l"(acc) : "l"(a), "l"(b));
}

// ---------------------------------------------------------------------------
// Prep: pack W1/W2 pairs + fold bw transforms. One block.
// ---------------------------------------------------------------------------
__global__ void pack_kernel(const float* __restrict__ W1,
                            const float* __restrict__ b1,
                            const float* __restrict__ W2,
                            const float* __restrict__ b2,
                            const float* __restrict__ bw) {
    int t = threadIdx.x;
    for (int i = t; i < CIN * (HH / 2); i += blockDim.x) {
        int c  = i / (HH / 2);
        int hp = i % (HH / 2);
        g_pack.w1t[i] = make_float2(W1[(2 * hp) * CIN + c],
                                    W1[(2 * hp + 1) * CIN + c]);
    }
    for (int i = t; i < HH * (COUT / 2); i += blockDim.x) {
        int h  = i / (COUT / 2);
        int op = i % (COUT / 2);
        g_pack.w2t[i] = make_float2(W2[(2 * op) * HH + h],
                                    W2[(2 * op + 1) * HH + h]);
    }
    if (t < HH) {
        g_pack.b1[t] = b1[t];
        float w = bw[t];
        float r = w * 0.3183098861837907f;          // bw/pi
        g_pack.sc[t] = sqrtf(r * r * r);
        g_pack.nb[t] = -w * 1.4426950408889634f;    // -bw*log2e
        g_pack.b2[t] = b2[t];
    }
}

// ---------------------------------------------------------------------------
// gemm1 fused (1 node/thread, f32x2, constant weights via LDCU):
//   m_h[g,h] = half((W1x+b1)*gw*sc[h]) ; acch[g,:]=0 ; grid4 pack.
// ---------------------------------------------------------------------------
__global__ void gemm1_kernel(const float* __restrict__ x,
                             const float* __restrict__ gw,
                             const float* __restrict__ grid) {
    int g = blockIdx.x * blockDim.x + threadIdx.x;   // node id
    int b = g >> 15;                                 // NN = 2^15
    int n = g & (NN - 1);
    const float* xb = x + (size_t)b * CIN * NN + n;

    const unsigned long long* w1u =
        reinterpret_cast<const unsigned long long*>(c_pack.w1t);

    unsigned long long acc2[HH / 2];
#pragma unroll
    for (int hp = 0; hp < HH / 2; hp++) acc2[hp] = 0ull;

#pragma unroll
    for (int c = 0; c < CIN; c++) {
        float xv = xb[(size_t)c * NN];               // coalesced
        unsigned long long xx = pk2(xv, xv);
#pragma unroll
        for (int hp = 0; hp < HH / 2; hp++)
            ffma2(acc2[hp], w1u[c * (HH / 2) + hp], xx);
    }

    float w = gw[g];
    uint4 ov[4];                                     // 32 halves = 64 B
    unsigned int* oh = reinterpret_cast<unsigned int*>(ov);
#pragma unroll
    for (int hp = 0; hp < HH / 2; hp++) {
        float2 a = upk2(acc2[hp]);
        float m0 = (a.x + c_pack.b1[2 * hp])     * w * c_pack.sc[2 * hp];
        float m1 = (a.y + c_pack.b1[2 * hp + 1]) * w * c_pack.sc[2 * hp + 1];
        __half2 h2 = __floats2half2_rn(m0, m1);
        oh[hp] = *reinterpret_cast<unsigned int*>(&h2);
    }
    uint4* mo = reinterpret_cast<uint4*>(g_mh + (size_t)g * HH);
#pragma unroll
    for (int q = 0; q < 4; q++) mo[q] = ov[q];

    // zero fp16 accumulator row (64 B)
    uint4* ao = reinterpret_cast<uint4*>(g_acch + (size_t)g * HH);
#pragma unroll
    for (int q = 0; q < 4; q++) ao[q] = make_uint4(0, 0, 0, 0);

    const float* gp = grid + (size_t)g * PP;
    g_grid4[g] = make_float4(gp[0], gp[1], gp[2], 0.f);
}

// ---------------------------------------------------------------------------
// Edge kernel — at the measured LTS-throughput cap (~6300 B/cyc chip-wide).
// Warp owns 32 edges; phase 1 (lane=edge) computes d2; phase 2 retires
// 8 edges/iter via red.global.add.noftz.v4.f16x2.
// ---------------------------------------------------------------------------
__global__ void edge_kernel(const int* __restrict__ es,
                            const int* __restrict__ ed) {
    __shared__ float4 stage[8][32];                  // 8 warps/block
    int tid  = blockIdx.x * blockDim.x + threadIdx.x;
    int lane = threadIdx.x & 31;
    int w    = threadIdx.x >> 5;

    // ---- phase 1: lane = edge ----
    int e   = tid;
    int b   = e >> 19;                               // NN*KK = 2^19
    int off = b << 15;                               // b * NN
    int s   = __ldg(es + e) + off;
    int d   = __ldg(ed + e) + off;

    float4 gs = g_grid4[s];
    float4 gd = g_grid4[d];
    float dx = gs.x - gd.x;
    float dy = gs.y - gd.y;
    float dz = gs.z - gd.z;
    float d2 = dx * dx + dy * dy + dz * dz;

    stage[w][lane] = make_float4(__int_as_float(s * HH),
                                 __int_as_float(d * HH), d2, 0.f);
    __syncwarp();

    // ---- phase 2: grp = edge of oct, c0 = first of 8 channels ----
    int grp = lane >> 2;                             // 0..7
    int c0  = (lane & 3) * 8;                        // 0,8,16,24

    float nb[8];
#pragma unroll
    for (int j = 0; j < 8; j++) nb[j] = c_pack.nb[c0 + j];

#pragma unroll
    for (int i = 0; i < 32; i += 8) {
        float4 p  = stage[w][i + grp];               // 8-way LDS.128 broadcast
        int   si  = __float_as_int(p.x);
        int   di  = __float_as_int(p.y);
        float d2i = p.z;

        uint4 mraw = *reinterpret_cast<const uint4*>(g_mh + si + c0);
        const __half2* mh2 = reinterpret_cast<const __half2*>(&mraw);

        unsigned int vpk[4];
#pragma unroll
        for (int j = 0; j < 4; j++) {
            float2 mf = __half22float2(mh2[j]);
            float e0, e1;
            asm("ex2.approx.f32 %0, %1;" : "=f"(e0) : "f"(nb[2 * j] * d2i));
            asm("ex2.approx.f32 %0, %1;" : "=f"(e1) : "f"(nb[2 * j + 1] * d2i));
            __half2 h2 = __floats2half2_rn(mf.x * e0, mf.y * e1);
            vpk[j] = *reinterpret_cast<unsigned int*>(&h2);
        }

        asm volatile("red.global.add.noftz.v4.f16x2 [%0], {%1, %2, %3, %4};"
                     :: "l"(g_acch + di + c0),
                        "r"(vpk[0]), "r"(vpk[1]), "r"(vpk[2]), "r"(vpk[3])
                     : "memory");
    }
}

// ---------------------------------------------------------------------------
// gemm2: TWO adjacent nodes per thread; each weight LDCU feeds two FFMA2s.
// acc rows = 128B contiguous load; outputs stored as float2 (STG.64).
// ---------------------------------------------------------------------------
__global__ void gemm2_kernel(float* __restrict__ out) {
    int t  = blockIdx.x * blockDim.x + threadIdx.x;  // pair id [0, GTOT/2)
    int g0 = 2 * t;                                  // nodes g0, g0+1 (same batch)
    int b  = g0 >> 15;
    int n  = g0 & (NN - 1);

    // load both fp16 acc rows (128 B contiguous)
    const uint4* av = reinterpret_cast<const uint4*>(g_acch + (size_t)g0 * HH);
    uint4 ra[8];
#pragma unroll
    for (int q = 0; q < 8; q++) ra[q] = av[q];
    const __half2* h0 = reinterpret_cast<const __half2*>(&ra[0]);  // node0
    const __half2* h1 = reinterpret_cast<const __half2*>(&ra[4]);  // node1

    const unsigned long long* w2u =
        reinterpret_cast<const unsigned long long*>(c_pack.w2t);

    unsigned long long sA[COUT / 2], sB[COUT / 2];   // per-node output pairs
#pragma unroll
    for (int op = 0; op < COUT / 2; op++) {
        unsigned long long binit = pk2(c_pack.b2[2 * op], c_pack.b2[2 * op + 1]);
        sA[op] = binit;
        sB[op] = binit;
    }

#pragma unroll
    for (int hp = 0; hp < HH / 2; hp++) {
        float2 f0 = __half22float2(h0[hp]);          // a0[2hp], a0[2hp+1]
        float2 f1 = __half22float2(h1[hp]);
        unsigned long long a0e = pk2(f0.x, f0.x);
        unsigned long long a0o = pk2(f0.y, f0.y);
        unsigned long long a1e = pk2(f1.x, f1.x);
        unsigned long long a1o = pk2(f1.y, f1.y);
        int he = 2 * hp, ho = 2 * hp + 1;
#pragma unroll
        for (int op = 0; op < COUT / 2; op++) {
            unsigned long long wE = w2u[he * (COUT / 2) + op];  // one LDCU
            ffma2(sA[op], wE, a0e);                              // two uses
            ffma2(sB[op], wE, a1e);
        }
#pragma unroll
        for (int op = 0; op < COUT / 2; op++) {
            unsigned long long wO = w2u[ho * (COUT / 2) + op];
            ffma2(sA[op], wO, a0o);
            ffma2(sB[op], wO, a1o);
        }
    }

    float* ob = out + (size_t)b * COUT * NN + n;
#pragma unroll
    for (int op = 0; op < COUT / 2; op++) {
        float2 vA = upk2(sA[op]);                    // node0: out[2op], out[2op+1]
        float2 vB = upk2(sB[op]);                    // node1
        *reinterpret_cast<float2*>(ob + (size_t)(2 * op) * NN) =
            make_float2(vA.x, vB.x);
        *reinterpret_cast<float2*>(ob + (size_t)(2 * op + 1) * NN) =
            make_float2(vA.y, vB.y);
    }
}

// ---------------------------------------------------------------------------
// Launcher
// inputs: 0:x 1:grid 2:grid_weight 3:edge_src 4:edge_dst 5:W1 6:b1 7:W2 8:b2 9:baseweight
// ---------------------------------------------------------------------------
extern "C" void kernel_launch(void* const* d_in, const int* in_sizes, int n_in,
                              void* d_out, int out_size) {
    const float* x    = (const float*)d_in[0];
    const float* grid = (const float*)d_in[1];
    const float* gw   = (const float*)d_in[2];
    const int*   es   = (const int*)d_in[3];
    const int*   ed   = (const int*)d_in[4];
    const float* W1   = (const float*)d_in[5];
    const float* b1   = (const float*)d_in[6];
    const float* W2   = (const float*)d_in[7];
    const float* b2   = (const float*)d_in[8];
    const float* bw   = (const float*)d_in[9];
    float* out = (float*)d_out;

    // 0) pack weights on device, stage into constant bank (single D2D copy)
    pack_kernel<<<1, 256>>>(W1, b1, W2, b2, bw);
    void* packAddr = nullptr;
    cudaGetSymbolAddress(&packAddr, g_pack);
    cudaMemcpyToSymbolAsync(c_pack, packAddr, sizeof(Pack), 0,
                            cudaMemcpyDeviceToDevice, 0);

    // 1) fused fc1 (f32x2) + gauss-norm + grid_weight ; zero acc ; pack grid
    gemm1_kernel<<<GTOT / 256, 256>>>(x, gw, grid);

    // 2) edge scatter: 32 edges per warp, two-phase, RED.v4.f16x2
    edge_kernel<<<ETOT / 256, 256>>>(es, ed);

    // 3) fc2 (f32x2, 2 nodes/thread) + transpose to (B, COUT, N)
    gemm2_kernel<<<(GTOT / 2) / 128, 128>>>(out);
}

// round 16
// speedup vs baseline: 1.1130x; 1.0222x over previous
#include <cuda_runtime.h>
#include <cuda_bf16.h>
#include <cuda_fp16.h>
#include <math.h>

// Fixed problem shape
#define BB   4
#define NN   32768
#define KK   16
#define CIN  32
#define HH   32
#define COUT 32
#define PP   3

#define GTOT (BB * NN)          // 131072 nodes
#define ETOT (BB * NN * KK)     // 2097152 edges
#define MELEMS (GTOT * HH)      // 4194304 elements

// Scratch (__device__ globals; no allocation allowed)
__device__ __half  g_mh[MELEMS];    // m[node,h] fp16 (8 MB)
__device__ __half  g_acch[MELEMS];  // segment-sum accumulator fp16 (8 MB)
__device__ float4  g_grid4[GTOT];   // packed grid coords

// Packed weights (pack_kernel fills g_pack; one D2D memcpy -> c_pack)
struct Pack {
    float2 w1t[CIN * (HH / 2)];    // [c][hp] = {W1[2hp,c], W1[2hp+1,c]}
    float2 w2t[HH * (COUT / 2)];   // [h][op] = {W2[2op,h], W2[2op+1,h]}
    float  b1[HH];
    float  sc[HH];                 // sqrt((bw/pi)^3)
    float  nb[HH];                 // -bw * log2(e)
    float  b2[COUT];
};
__device__  Pack g_pack;
__constant__ Pack c_pack;

// ---- f32x2 helpers (sm_103a packed fp32 pipe) ----
__device__ __forceinline__ unsigned long long pk2(float lo, float hi) {
    unsigned long long r;
    asm("mov.b64 %0, {%1,%2};" : "=l"(r) : "f"(lo), "f"(hi));
    return r;
}
__device__ __forceinline__ float2 upk2(unsigned long long v) {
    float2 r;
    asm("mov.b64 {%0,%1}, %2;" : "=f"(r.x), "=f"(r.y) : "l"(v));
    return r;
}
__device__ __forceinline__ void ffma2(unsigned long long& acc,
                                      unsigned long long a,
                                      unsigned long long b) {
    asm("fma.rn.f32x2 %0, %1, %2, %0;" : "+l"(acc) : "l"(a), "l"(b));
}

// ---------------------------------------------------------------------------
// Prep: pack W1/W2 pairs + fold bw transforms. One block.
// ---------------------------------------------------------------------------
__global__ void pack_kernel(const float* __restrict__ W1,
                            const float* __restrict__ b1,
                            const float* __restrict__ W2,
                            const float* __restrict__ b2,
                            const float* __restrict__ bw) {
    int t = threadIdx.x;
    for (int i = t; i < CIN * (HH / 2); i += blockDim.x) {
        int c  = i / (HH / 2);
        int hp = i % (HH / 2);
        g_pack.w1t[i] = make_float2(W1[(2 * hp) * CIN + c],
                                    W1[(2 * hp + 1) * CIN + c]);
    }
    for (int i = t; i < HH * (COUT / 2); i += blockDim.x) {
        int h  = i / (COUT / 2);
        int op = i % (COUT / 2);
        g_pack.w2t[i] = make_float2(W2[(2 * op) * HH + h],
                                    W2[(2 * op + 1) * HH + h]);
    }
    if (t < HH) {
        g_pack.b1[t] = b1[t];
        float w = bw[t];
        float r = w * 0.3183098861837907f;          // bw/pi
        g_pack.sc[t] = sqrtf(r * r * r);
        g_pack.nb[t] = -w * 1.4426950408889634f;    // -bw*log2e
        g_pack.b2[t] = b2[t];
    }
}

// ---------------------------------------------------------------------------
// gemm1 fused (1 node/thread, f32x2, constant weights via LDCU):
//   m_h[g,h] = half((W1x+b1)*gw*sc[h]) ; acch[g,:]=0 ; grid4 pack.
// ---------------------------------------------------------------------------
__global__ void gemm1_kernel(const float* __restrict__ x,
                             const float* __restrict__ gw,
                             const float* __restrict__ grid) {
    int g = blockIdx.x * blockDim.x + threadIdx.x;   // node id
    int b = g >> 15;                                 // NN = 2^15
    int n = g & (NN - 1);
    const float* xb = x + (size_t)b * CIN * NN + n;

    const unsigned long long* w1u =
        reinterpret_cast<const unsigned long long*>(c_pack.w1t);

    unsigned long long acc2[HH / 2];
#pragma unroll
    for (int hp = 0; hp < HH / 2; hp++) acc2[hp] = 0ull;

#pragma unroll
    for (int c = 0; c < CIN; c++) {
        float xv = xb[(size_t)c * NN];               // coalesced
        unsigned long long xx = pk2(xv, xv);
#pragma unroll
        for (int hp = 0; hp < HH / 2; hp++)
            ffma2(acc2[hp], w1u[c * (HH / 2) + hp], xx);
    }

    float w = gw[g];
    uint4 ov[4];                                     // 32 halves = 64 B
    unsigned int* oh = reinterpret_cast<unsigned int*>(ov);
#pragma unroll
    for (int hp = 0; hp < HH / 2; hp++) {
        float2 a = upk2(acc2[hp]);
        float m0 = (a.x + c_pack.b1[2 * hp])     * w * c_pack.sc[2 * hp];
        float m1 = (a.y + c_pack.b1[2 * hp + 1]) * w * c_pack.sc[2 * hp + 1];
        __half2 h2 = __floats2half2_rn(m0, m1);
        oh[hp] = *reinterpret_cast<unsigned int*>(&h2);
    }
    uint4* mo = reinterpret_cast<uint4*>(g_mh + (size_t)g * HH);
#pragma unroll
    for (int q = 0; q < 4; q++) mo[q] = ov[q];

    // zero fp16 accumulator row (64 B)
    uint4* ao = reinterpret_cast<uint4*>(g_acch + (size_t)g * HH);
#pragma unroll
    for (int q = 0; q < 4; q++) ao[q] = make_uint4(0, 0, 0, 0);

    const float* gp = grid + (size_t)g * PP;
    g_grid4[g] = make_float4(gp[0], gp[1], gp[2], 0.f);
}

// ---------------------------------------------------------------------------
// Edge kernel — at the measured LTS-throughput cap (~6300 B/cyc chip-wide).
// Warp owns 32 edges; phase 1 (lane=edge) computes d2; phase 2 retires
// 8 edges/iter via red.global.add.noftz.v4.f16x2.
// ---------------------------------------------------------------------------
__global__ void edge_kernel(const int* __restrict__ es,
                            const int* __restrict__ ed) {
    __shared__ float4 stage[8][32];                  // 8 warps/block
    int tid  = blockIdx.x * blockDim.x + threadIdx.x;
    int lane = threadIdx.x & 31;
    int w    = threadIdx.x >> 5;

    // ---- phase 1: lane = edge ----
    int e   = tid;
    int b   = e >> 19;                               // NN*KK = 2^19
    int off = b << 15;                               // b * NN
    int s   = __ldg(es + e) + off;
    int d   = __ldg(ed + e) + off;

    float4 gs = g_grid4[s];
    float4 gd = g_grid4[d];
    float dx = gs.x - gd.x;
    float dy = gs.y - gd.y;
    float dz = gs.z - gd.z;
    float d2 = dx * dx + dy * dy + dz * dz;

    stage[w][lane] = make_float4(__int_as_float(s * HH),
                                 __int_as_float(d * HH), d2, 0.f);
    __syncwarp();

    // ---- phase 2: grp = edge of oct, c0 = first of 8 channels ----
    int grp = lane >> 2;                             // 0..7
    int c0  = (lane & 3) * 8;                        // 0,8,16,24

    float nb[8];
#pragma unroll
    for (int j = 0; j < 8; j++) nb[j] = c_pack.nb[c0 + j];

#pragma unroll
    for (int i = 0; i < 32; i += 8) {
        float4 p  = stage[w][i + grp];               // 8-way LDS.128 broadcast
        int   si  = __float_as_int(p.x);
        int   di  = __float_as_int(p.y);
        float d2i = p.z;

        uint4 mraw = *reinterpret_cast<const uint4*>(g_mh + si + c0);
        const __half2* mh2 = reinterpret_cast<const __half2*>(&mraw);

        unsigned int vpk[4];
#pragma unroll
        for (int j = 0; j < 4; j++) {
            float2 mf = __half22float2(mh2[j]);
            float e0, e1;
            asm("ex2.approx.f32 %0, %1;" : "=f"(e0) : "f"(nb[2 * j] * d2i));
            asm("ex2.approx.f32 %0, %1;" : "=f"(e1) : "f"(nb[2 * j + 1] * d2i));
            __half2 h2 = __floats2half2_rn(mf.x * e0, mf.y * e1);
            vpk[j] = *reinterpret_cast<unsigned int*>(&h2);
        }

        asm volatile("red.global.add.noftz.v4.f16x2 [%0], {%1, %2, %3, %4};"
                     :: "l"(g_acch + di + c0),
                        "r"(vpk[0]), "r"(vpk[1]), "r"(vpk[2]), "r"(vpk[3])
                     : "memory");
    }
}

// ---------------------------------------------------------------------------
// gemm2: TWO adjacent nodes per thread; each weight LDCU feeds two FFMA2s.
// acc rows = 128B contiguous load; outputs stored as float2 (STG.64).
// ---------------------------------------------------------------------------
__global__ void gemm2_kernel(float* __restrict__ out) {
    int t  = blockIdx.x * blockDim.x + threadIdx.x;  // pair id [0, GTOT/2)
    int g0 = 2 * t;                                  // nodes g0, g0+1 (same batch)
    int b  = g0 >> 15;
    int n  = g0 & (NN - 1);

    // load both fp16 acc rows (128 B contiguous)
    const uint4* av = reinterpret_cast<const uint4*>(g_acch + (size_t)g0 * HH);
    uint4 ra[8];
#pragma unroll
    for (int q = 0; q < 8; q++) ra[q] = av[q];
    const __half2* h0 = reinterpret_cast<const __half2*>(&ra[0]);  // node0
    const __half2* h1 = reinterpret_cast<const __half2*>(&ra[4]);  // node1

    const unsigned long long* w2u =
        reinterpret_cast<const unsigned long long*>(c_pack.w2t);

    unsigned long long sA[COUT / 2], sB[COUT / 2];   // per-node output pairs
#pragma unroll
    for (int op = 0; op < COUT / 2; op++) {
        unsigned long long binit = pk2(c_pack.b2[2 * op], c_pack.b2[2 * op + 1]);
        sA[op] = binit;
        sB[op] = binit;
    }

#pragma unroll
    for (int hp = 0; hp < HH / 2; hp++) {
        float2 f0 = __half22float2(h0[hp]);          // a0[2hp], a0[2hp+1]
        float2 f1 = __half22float2(h1[hp]);
        unsigned long long a0e = pk2(f0.x, f0.x);
        unsigned long long a0o = pk2(f0.y, f0.y);
        unsigned long long a1e = pk2(f1.x, f1.x);
        unsigned long long a1o = pk2(f1.y, f1.y);
        int he = 2 * hp, ho = 2 * hp + 1;
#pragma unroll
        for (int op = 0; op < COUT / 2; op++) {
            unsigned long long wE = w2u[he * (COUT / 2) + op];  // one LDCU
            ffma2(sA[op], wE, a0e);                              // two uses
            ffma2(sB[op], wE, a1e);
        }
#pragma unroll
        for (int op = 0; op < COUT / 2; op++) {
            unsigned long long wO = w2u[ho * (COUT / 2) + op];
            ffma2(sA[op], wO, a0o);
            ffma2(sB[op], wO, a1o);
        }
    }

    float* ob = out + (size_t)b * COUT * NN + n;
#pragma unroll
    for (int op = 0; op < COUT / 2; op++) {
        float2 vA = upk2(sA[op]);                    // node0: out[2op], out[2op+1]
        float2 vB = upk2(sB[op]);                    // node1
        *reinterpret_cast<float2*>(ob + (size_t)(2 * op) * NN) =
            make_float2(vA.x, vB.x);
        *reinterpret_cast<float2*>(ob + (size_t)(2 * op + 1) * NN) =
            make_float2(vA.y, vB.y);
    }
}

// ---------------------------------------------------------------------------
// Launcher
// inputs: 0:x 1:grid 2:grid_weight 3:edge_src 4:edge_dst 5:W1 6:b1 7:W2 8:b2 9:baseweight
// ---------------------------------------------------------------------------
extern "C" void kernel_launch(void* const* d_in, const int* in_sizes, int n_in,
                              void* d_out, int out_size) {
    const float* x    = (const float*)d_in[0];
    const float* grid = (const float*)d_in[1];
    const float* gw   = (const float*)d_in[2];
    const int*   es   = (const int*)d_in[3];
    const int*   ed   = (const int*)d_in[4];
    const float* W1   = (const float*)d_in[5];
    const float* b1   = (const float*)d_in[6];
    const float* W2   = (const float*)d_in[7];
    const float* b2   = (const float*)d_in[8];
    const float* bw   = (const float*)d_in[9];
    float* out = (float*)d_out;

    // 0) pack weights on device, stage into constant bank (single D2D copy)
    pack_kernel<<<1, 256>>>(W1, b1, W2, b2, bw);
    void* packAddr = nullptr;
    cudaGetSymbolAddress(&packAddr, g_pack);
    cudaMemcpyToSymbolAsync(c_pack, packAddr, sizeof(Pack), 0,
                            cudaMemcpyDeviceToDevice, 0);

    // 1) fused fc1 (f32x2) + gauss-norm + grid_weight ; zero acc ; pack grid
    gemm1_kernel<<<GTOT / 256, 256>>>(x, gw, grid);

    // 2) edge scatter: 32 edges per warp, two-phase, RED.v4.f16x2
    edge_kernel<<<ETOT / 256, 256>>>(es, ed);

    // 3) fc2 (f32x2, 2 nodes/thread) + transpose to (B, COUT, N)
    gemm2_kernel<<<(GTOT / 2) / 128, 128>>>(out);
}

// round 17
// speedup vs baseline: 1.1135x; 1.0004x over previous
#include <cuda_runtime.h>
#include <cuda_bf16.h>
#include <cuda_fp16.h>
#include <math.h>

// Fixed problem shape
#define BB   4
#define NN   32768
#define KK   16
#define CIN  32
#define HH   32
#define COUT 32
#define PP   3

#define GTOT (BB * NN)          // 131072 nodes
#define ETOT (BB * NN * KK)     // 2097152 edges
#define MELEMS (GTOT * HH)      // 4194304 elements

// Scratch (__device__ globals; no allocation allowed)
__device__ __half  g_mh[MELEMS];    // m[node,h] fp16 (8 MB)
__device__ __half  g_acch[MELEMS];  // segment-sum accumulator fp16 (8 MB)
__device__ float4  g_grid4[GTOT];   // packed grid coords

// Packed weights (pack_kernel fills g_pack; one D2D memcpy -> c_pack)
struct Pack {
    float2 w1t[CIN * (HH / 2)];    // [c][hp] = {W1[2hp,c], W1[2hp+1,c]}
    float2 w2t[HH * (COUT / 2)];   // [h][op] = {W2[2op,h], W2[2op+1,h]}
    float  b1[HH];
    float  sc[HH];                 // sqrt((bw/pi)^3)
    float  nb[HH];                 // -bw * log2(e)
    float  b2[COUT];
};
__device__  Pack g_pack;
__constant__ Pack c_pack;

// ---- f32x2 helpers (sm_103a packed fp32 pipe) ----
__device__ __forceinline__ unsigned long long pk2(float lo, float hi) {
    unsigned long long r;
    asm("mov.b64 %0, {%1,%2};" : "=l"(r) : "f"(lo), "f"(hi));
    return r;
}
__device__ __forceinline__ float2 upk2(unsigned long long v) {
    float2 r;
    asm("mov.b64 {%0,%1}, %2;" : "=f"(r.x), "=f"(r.y) : "l"(v));
    return r;
}
__device__ __forceinline__ void ffma2(unsigned long long& acc,
                                      unsigned long long a,
                                      unsigned long long b) {
    asm("fma.rn.f32x2 %0, %1, %2, %0;" : "+l"(acc) : "l"(a), "l"(b));
}

// ---------------------------------------------------------------------------
// Prep: pack W1/W2 pairs + fold bw transforms. One block.
// ---------------------------------------------------------------------------
__global__ void pack_kernel(const float* __restrict__ W1,
                            const float* __restrict__ b1,
                            const float* __restrict__ W2,
                            const float* __restrict__ b2,
                            const float* __restrict__ bw) {
    int t = threadIdx.x;
    for (int i = t; i < CIN * (HH / 2); i += blockDim.x) {
        int c  = i / (HH / 2);
        int hp = i % (HH / 2);
        g_pack.w1t[i] = make_float2(W1[(2 * hp) * CIN + c],
                                    W1[(2 * hp + 1) * CIN + c]);
    }
    for (int i = t; i < HH * (COUT / 2); i += blockDim.x) {
        int h  = i / (COUT / 2);
        int op = i % (COUT / 2);
        g_pack.w2t[i] = make_float2(W2[(2 * op) * HH + h],
                                    W2[(2 * op + 1) * HH + h]);
    }
    if (t < HH) {
        g_pack.b1[t] = b1[t];
        float w = bw[t];
        float r = w * 0.3183098861837907f;          // bw/pi
        g_pack.sc[t] = sqrtf(r * r * r);
        g_pack.nb[t] = -w * 1.4426950408889634f;    // -bw*log2e
        g_pack.b2[t] = b2[t];
    }
}

// ---------------------------------------------------------------------------
// gemm1 fused (1 node/thread, f32x2, constant weights via LDCU):
//   m_h[g,h] = half((W1x+b1)*gw*sc[h]) ; acch[g,:]=0 ; grid4 pack.
// ---------------------------------------------------------------------------
__global__ void gemm1_kernel(const float* __restrict__ x,
                             const float* __restrict__ gw,
                             const float* __restrict__ grid) {
    int g = blockIdx.x * blockDim.x + threadIdx.x;   // node id
    int b = g >> 15;                                 // NN = 2^15
    int n = g & (NN - 1);
    const float* xb = x + (size_t)b * CIN * NN + n;

    const unsigned long long* w1u =
        reinterpret_cast<const unsigned long long*>(c_pack.w1t);

    unsigned long long acc2[HH / 2];
#pragma unroll
    for (int hp = 0; hp < HH / 2; hp++) acc2[hp] = 0ull;

#pragma unroll
    for (int c = 0; c < CIN; c++) {
        float xv = xb[(size_t)c * NN];               // coalesced
        unsigned long long xx = pk2(xv, xv);
#pragma unroll
        for (int hp = 0; hp < HH / 2; hp++)
            ffma2(acc2[hp], w1u[c * (HH / 2) + hp], xx);
    }

    float w = gw[g];
    uint4 ov[4];                                     // 32 halves = 64 B
    unsigned int* oh = reinterpret_cast<unsigned int*>(ov);
#pragma unroll
    for (int hp = 0; hp < HH / 2; hp++) {
        float2 a = upk2(acc2[hp]);
        float m0 = (a.x + c_pack.b1[2 * hp])     * w * c_pack.sc[2 * hp];
        float m1 = (a.y + c_pack.b1[2 * hp + 1]) * w * c_pack.sc[2 * hp + 1];
        __half2 h2 = __floats2half2_rn(m0, m1);
        oh[hp] = *reinterpret_cast<unsigned int*>(&h2);
    }
    uint4* mo = reinterpret_cast<uint4*>(g_mh + (size_t)g * HH);
#pragma unroll
    for (int q = 0; q < 4; q++) mo[q] = ov[q];

    // zero fp16 accumulator row (64 B)
    uint4* ao = reinterpret_cast<uint4*>(g_acch + (size_t)g * HH);
#pragma unroll
    for (int q = 0; q < 4; q++) ao[q] = make_uint4(0, 0, 0, 0);

    const float* gp = grid + (size_t)g * PP;
    g_grid4[g] = make_float4(gp[0], gp[1], gp[2], 0.f);
}

// ---------------------------------------------------------------------------
// Edge kernel — at the measured LTS-throughput cap (~6300 B/cyc chip-wide).
// Warp owns 32 edges; phase 1 (lane=edge) computes d2; phase 2 retires
// 8 edges/iter via red.global.add.noftz.v4.f16x2.
// ---------------------------------------------------------------------------
__global__ void edge_kernel(const int* __restrict__ es,
                            const int* __restrict__ ed) {
    __shared__ float4 stage[8][32];                  // 8 warps/block
    int tid  = blockIdx.x * blockDim.x + threadIdx.x;
    int lane = threadIdx.x & 31;
    int w    = threadIdx.x >> 5;

    // ---- phase 1: lane = edge ----
    int e   = tid;
    int b   = e >> 19;                               // NN*KK = 2^19
    int off = b << 15;                               // b * NN
    int s   = __ldg(es + e) + off;
    int d   = __ldg(ed + e) + off;

    float4 gs = g_grid4[s];
    float4 gd = g_grid4[d];
    float dx = gs.x - gd.x;
    float dy = gs.y - gd.y;
    float dz = gs.z - gd.z;
    float d2 = dx * dx + dy * dy + dz * dz;

    stage[w][lane] = make_float4(__int_as_float(s * HH),
                                 __int_as_float(d * HH), d2, 0.f);
    __syncwarp();

    // ---- phase 2: grp = edge of oct, c0 = first of 8 channels ----
    int grp = lane >> 2;                             // 0..7
    int c0  = (lane & 3) * 8;                        // 0,8,16,24

    float nb[8];
#pragma unroll
    for (int j = 0; j < 8; j++) nb[j] = c_pack.nb[c0 + j];

#pragma unroll
    for (int i = 0; i < 32; i += 8) {
        float4 p  = stage[w][i + grp];               // 8-way LDS.128 broadcast
        int   si  = __float_as_int(p.x);
        int   di  = __float_as_int(p.y);
        float d2i = p.z;

        uint4 mraw = *reinterpret_cast<const uint4*>(g_mh + si + c0);
        const __half2* mh2 = reinterpret_cast<const __half2*>(&mraw);

        unsigned int vpk[4];
#pragma unroll
        for (int j = 0; j < 4; j++) {
            float2 mf = __half22float2(mh2[j]);
            float e0, e1;
            asm("ex2.approx.f32 %0, %1;" : "=f"(e0) : "f"(nb[2 * j] * d2i));
            asm("ex2.approx.f32 %0, %1;" : "=f"(e1) : "f"(nb[2 * j + 1] * d2i));
            __half2 h2 = __floats2half2_rn(mf.x * e0, mf.y * e1);
            vpk[j] = *reinterpret_cast<unsigned int*>(&h2);
        }

        asm volatile("red.global.add.noftz.v4.f16x2 [%0], {%1, %2, %3, %4};"
                     :: "l"(g_acch + di + c0),
                        "r"(vpk[0]), "r"(vpk[1]), "r"(vpk[2]), "r"(vpk[3])
                     : "memory");
    }
}

// ---------------------------------------------------------------------------
// gemm2: TWO adjacent nodes per thread; each weight LDCU feeds two FFMA2s.
// acc rows = 128B contiguous load; outputs stored as float2 (STG.64).
// ---------------------------------------------------------------------------
__global__ void gemm2_kernel(float* __restrict__ out) {
    int t  = blockIdx.x * blockDim.x + threadIdx.x;  // pair id [0, GTOT/2)
    int g0 = 2 * t;                                  // nodes g0, g0+1 (same batch)
    int b  = g0 >> 15;
    int n  = g0 & (NN - 1);

    // load both fp16 acc rows (128 B contiguous)
    const uint4* av = reinterpret_cast<const uint4*>(g_acch + (size_t)g0 * HH);
    uint4 ra[8];
#pragma unroll
    for (int q = 0; q < 8; q++) ra[q] = av[q];
    const __half2* h0 = reinterpret_cast<const __half2*>(&ra[0]);  // node0
    const __half2* h1 = reinterpret_cast<const __half2*>(&ra[4]);  // node1

    const unsigned long long* w2u =
        reinterpret_cast<const unsigned long long*>(c_pack.w2t);

    unsigned long long sA[COUT / 2], sB[COUT / 2];   // per-node output pairs
#pragma unroll
    for (int op = 0; op < COUT / 2; op++) {
        unsigned long long binit = pk2(c_pack.b2[2 * op], c_pack.b2[2 * op + 1]);
        sA[op] = binit;
        sB[op] = binit;
    }

#pragma unroll
    for (int hp = 0; hp < HH / 2; hp++) {
        float2 f0 = __half22float2(h0[hp]);          // a0[2hp], a0[2hp+1]
        float2 f1 = __half22float2(h1[hp]);
        unsigned long long a0e = pk2(f0.x, f0.x);
        unsigned long long a0o = pk2(f0.y, f0.y);
        unsigned long long a1e = pk2(f1.x, f1.x);
        unsigned long long a1o = pk2(f1.y, f1.y);
        int he = 2 * hp, ho = 2 * hp + 1;
#pragma unroll
        for (int op = 0; op < COUT / 2; op++) {
            unsigned long long wE = w2u[he * (COUT / 2) + op];  // one LDCU
            ffma2(sA[op], wE, a0e);                              // two uses
            ffma2(sB[op], wE, a1e);
        }
#pragma unroll
        for (int op = 0; op < COUT / 2; op++) {
            unsigned long long wO = w2u[ho * (COUT / 2) + op];
            ffma2(sA[op], wO, a0o);
            ffma2(sB[op], wO, a1o);
        }
    }

    float* ob = out + (size_t)b * COUT * NN + n;
#pragma unroll
    for (int op = 0; op < COUT / 2; op++) {
        float2 vA = upk2(sA[op]);                    // node0: out[2op], out[2op+1]
        float2 vB = upk2(sB[op]);                    // node1
        *reinterpret_cast<float2*>(ob + (size_t)(2 * op) * NN) =
            make_float2(vA.x, vB.x);
        *reinterpret_cast<float2*>(ob + (size_t)(2 * op + 1) * NN) =
            make_float2(vA.y, vB.y);
    }
}

// ---------------------------------------------------------------------------
// Launcher
// inputs: 0:x 1:grid 2:grid_weight 3:edge_src 4:edge_dst 5:W1 6:b1 7:W2 8:b2 9:baseweight
// ---------------------------------------------------------------------------
extern "C" void kernel_launch(void* const* d_in, const int* in_sizes, int n_in,
                              void* d_out, int out_size) {
    const float* x    = (const float*)d_in[0];
    const float* grid = (const float*)d_in[1];
    const float* gw   = (const float*)d_in[2];
    const int*   es   = (const int*)d_in[3];
    const int*   ed   = (const int*)d_in[4];
    const float* W1   = (const float*)d_in[5];
    const float* b1   = (const float*)d_in[6];
    const float* W2   = (const float*)d_in[7];
    const float* b2   = (const float*)d_in[8];
    const float* bw   = (const float*)d_in[9];
    float* out = (float*)d_out;

    // 0) pack weights on device, stage into constant bank (single D2D copy)
    pack_kernel<<<1, 256>>>(W1, b1, W2, b2, bw);
    void* packAddr = nullptr;
    cudaGetSymbolAddress(&packAddr, g_pack);
    cudaMemcpyToSymbolAsync(c_pack, packAddr, sizeof(Pack), 0,
                            cudaMemcpyDeviceToDevice, 0);

    // 1) fused fc1 (f32x2) + gauss-norm + grid_weight ; zero acc ; pack grid
    gemm1_kernel<<<GTOT / 256, 256>>>(x, gw, grid);

    // 2) edge scatter: 32 edges per warp, two-phase, RED.v4.f16x2
    edge_kernel<<<ETOT / 256, 256>>>(es, ed);

    // 3) fc2 (f32x2, 2 nodes/thread) + transpose to (B, COUT, N)
    gemm2_kernel<<<(GTOT / 2) / 128, 128>>>(out);
}